// round 7
// baseline (speedup 1.0000x reference)
#include <cuda_runtime.h>
#include <math.h>

typedef unsigned long long ull;

#define Bq   256
#define Tq   512
#define Dq   256
#define Hq   512
#define F1q  128
#define Oq   64
#define BHq  (Bq*Hq)
#define NBLK_SCAN 128
#define WST  68                 // persistent W smem stride (floats)
#define ASTd 136                // duplicated-A smem stride (floats) per k-slice
#define SCHd (16*ASTd)          // one dup-A chunk
#define SCH  (16*68)            // legacy chunk (head kernels)
#define SMEM_SCAN ((Hq*WST + 2*SCHd) * 4)   // 156,672 B

// ---------------- scratch (device globals: allocation-free rule) ----------------
__device__ float g_pre0r[4*BHq];   // 4-slot rings (each 512 KB; all L2-resident)
__device__ float g_h0r[4*BHq];
__device__ float g_p1r[4*BHq];
__device__ float g_h1r[4*BHq];
__device__ float g_z1[Bq*F1q];
__device__ unsigned g_count;
__device__ volatile unsigned g_sense;

// produced/consumed counters, indexed [t*4 + band]
__device__ int f_prod_pre0[Tq*4];
__device__ int f_prod_h0 [Tq*4];
__device__ int f_prod_p1 [Tq*4];
__device__ int f_prod_h1 [Tq*4];
__device__ int f_cons_pre0[Tq*4];
__device__ int f_cons_p1 [Tq*4];
__device__ int f_cons_h0 [(Tq+1)*4];   // index (t+1): slot for "consumed h0[t]"
__device__ int f_cons_h1 [(Tq+1)*4];

// ---------------- packed f32x2 helpers ----------------
__device__ __forceinline__ ull pack2(float lo, float hi)
{
    ull v;
    asm("mov.b64 %0, {%1, %2};" : "=l"(v) : "f"(lo), "f"(hi));
    return v;
}
__device__ __forceinline__ void unpack2(ull v, float &lo, float &hi)
{
    asm("mov.b64 {%0, %1}, %2;" : "=f"(lo), "=f"(hi) : "l"(v));
}
__device__ __forceinline__ void ffma2(ull &d, ull a, ull b)
{
    asm("fma.rn.f32x2 %0, %1, %2, %0;" : "+l"(d) : "l"(a), "l"(b));
}

// ---------------- flag wait (volatile L2 poll, thread-0 only) ----------------
__device__ __forceinline__ void wait_flag(const int* p, int target)
{
    const volatile int* vp = (const volatile int*)p;
    while (*vp < target) __nanosleep(20);
}

// ---------------- one-time grid barrier for init ----------------
__device__ __forceinline__ void grid_barrier_once(unsigned nblk)
{
    __syncthreads();
    if (threadIdx.x == 0) {
        if (atomicAdd(&g_count, 1u) == nblk - 1u) {
            __threadfence();
            g_sense = 1u;
        } else {
            while (g_sense != 1u) { __nanosleep(32); }
        }
    }
    __syncthreads();
}

// ======== scan GEMM core, persistent-W + duplicated-A smem ========
// C(64x64) = A(rows m0.., K) * Wsmem^T. 256 thr, thread (tx,ty) owns 4x4.
// Inner loop per k: 2 LDS.128 (dup A rows) + 1 LDS.128 (W col-pairs) + 8 FFMA2.
__device__ __forceinline__ void gemm64_wp(const float* __restrict__ A, int lda, int m0,
                                          const float* __restrict__ sW, int K,
                                          float* sA, float accf[4][4])
{
    const int tid  = threadIdx.x;
    const int tx   = tid & 15, ty = tid >> 4;
    const int lrow = tid >> 2;          // 0..63
    const int lcg  = (tid & 3) << 2;    // 0,4,8,12
    const float* ap = A + (size_t)(m0 + lrow) * lda + lcg;

    ull acc[4][2];
    #pragma unroll
    for (int i = 0; i < 4; ++i) { acc[i][0] = 0ull; acc[i][1] = 0ull; }

    float4 av0 = __ldcg((const float4*)ap);
    float4 av1 = __ldcg((const float4*)(ap + 16));

    int buf = 0;
    for (int kc = 0; kc < K; kc += 16, buf ^= 1) {
        float* sAb = sA + buf * SCHd;
        // duplicated stores: each A value written as an (a,a) pair
        *(ull*)(sAb + (lcg+0)*ASTd + 2*lrow) = pack2(av0.x, av0.x);
        *(ull*)(sAb + (lcg+1)*ASTd + 2*lrow) = pack2(av0.y, av0.y);
        *(ull*)(sAb + (lcg+2)*ASTd + 2*lrow) = pack2(av0.z, av0.z);
        *(ull*)(sAb + (lcg+3)*ASTd + 2*lrow) = pack2(av0.w, av0.w);
        __syncthreads();
        av0 = av1;
        if (kc + 32 < K)
            av1 = __ldcg((const float4*)(ap + kc + 32));
        const float* sWk = sW + kc * WST;
        #pragma unroll
        for (int k = 0; k < 16; ++k) {
            const float* arow = sAb + k*ASTd + (ty << 3);
            ulonglong2 a01 = *(const ulonglong2*)arow;        // dup rows 4ty+0, 4ty+1
            ulonglong2 a23 = *(const ulonglong2*)(arow + 4);  // dup rows 4ty+2, 4ty+3
            ulonglong2 wv  = *(const ulonglong2*)(sWk + k*WST + (tx << 2)); // col pairs
            ffma2(acc[0][0], a01.x, wv.x); ffma2(acc[0][1], a01.x, wv.y);
            ffma2(acc[1][0], a01.y, wv.x); ffma2(acc[1][1], a01.y, wv.y);
            ffma2(acc[2][0], a23.x, wv.x); ffma2(acc[2][1], a23.x, wv.y);
            ffma2(acc[3][0], a23.y, wv.x); ffma2(acc[3][1], a23.y, wv.y);
        }
        // next store targets the other buffer; ordered by the next sync.
    }

    #pragma unroll
    for (int i = 0; i < 4; ++i) {
        unpack2(acc[i][0], accf[i][0], accf[i][1]);
        unpack2(acc[i][1], accf[i][2], accf[i][3]);
    }
}

// preload one 64-row W tile (rows n0.., K cols) into sW[k*WST + n]
__device__ __forceinline__ void preload_W(const float* __restrict__ W, int ldw, int n0,
                                          int K, float* sW)
{
    const int KQ = K >> 2;
    for (int i = threadIdx.x; i < (KQ << 6); i += 256) {
        int n  = i / KQ;
        int k4 = i - n * KQ;
        float4 v = *(const float4*)(W + (size_t)(n0 + n) * ldw + (k4 << 2));
        sW[(4*k4+0)*WST + n] = v.x;
        sW[(4*k4+1)*WST + n] = v.y;
        sW[(4*k4+2)*WST + n] = v.z;
        sW[(4*k4+3)*WST + n] = v.w;
    }
}

// ---------------- legacy chunked GEMM core (tiny head kernels) ----------------
__device__ __forceinline__ void gemm64s(const float* __restrict__ A, int lda, int m0,
                                        const float* __restrict__ W, int ldw, int n0,
                                        int K, float* sA, float* sW, float accf[4][4])
{
    const int tid  = threadIdx.x;
    const int tx   = tid & 15, ty = tid >> 4;
    const int lrow = tid >> 2;
    const int lcg  = (tid & 3) << 2;
    const float* ap = A + (size_t)(m0 + lrow) * lda + lcg;
    const float* wp = W + (size_t)(n0 + lrow) * ldw + lcg;

    ull acc[2][4];
    #pragma unroll
    for (int i = 0; i < 2; ++i)
        #pragma unroll
        for (int j = 0; j < 4; ++j) acc[i][j] = 0ull;

    float4 av = __ldcg((const float4*)ap);
    float4 wv = *(const float4*)wp;

    int buf = 0;
    for (int kc = 0; kc < K; kc += 16, buf ^= 1) {
        float* sAb = sA + buf * SCH;
        float* sWb = sW + buf * SCH;
        sAb[(lcg+0)*68 + lrow] = av.x;
        sAb[(lcg+1)*68 + lrow] = av.y;
        sAb[(lcg+2)*68 + lrow] = av.z;
        sAb[(lcg+3)*68 + lrow] = av.w;
        sWb[(lcg+0)*68 + lrow] = wv.x;
        sWb[(lcg+1)*68 + lrow] = wv.y;
        sWb[(lcg+2)*68 + lrow] = wv.z;
        sWb[(lcg+3)*68 + lrow] = wv.w;
        __syncthreads();
        if (kc + 16 < K) {
            av = __ldcg((const float4*)(ap + kc + 16));
            wv = *(const float4*)(wp + kc + 16);
        }
        #pragma unroll
        for (int k = 0; k < 16; ++k) {
            const float* ar = sAb + k*68 + (ty << 2);
            ull a01 = *(const ull*)ar;
            ull a23 = *(const ull*)(ar + 2);
            float4 w = *(const float4*)(sWb + k*68 + (tx << 2));
            ull b0 = pack2(w.x, w.x);
            ull b1 = pack2(w.y, w.y);
            ull b2 = pack2(w.z, w.z);
            ull b3 = pack2(w.w, w.w);
            ffma2(acc[0][0], a01, b0); ffma2(acc[0][1], a01, b1);
            ffma2(acc[0][2], a01, b2); ffma2(acc[0][3], a01, b3);
            ffma2(acc[1][0], a23, b0); ffma2(acc[1][1], a23, b1);
            ffma2(acc[1][2], a23, b2); ffma2(acc[1][3], a23, b3);
        }
    }

    #pragma unroll
    for (int i = 0; i < 2; ++i)
        #pragma unroll
        for (int j = 0; j < 4; ++j)
            unpack2(acc[i][j], accf[2*i][j], accf[2*i + 1][j]);
}

// ---------------- reset counters/flags ----------------
__global__ void k_reset()
{
    int i = blockIdx.x*blockDim.x + threadIdx.x;
    int stride = gridDim.x*blockDim.x;
    if (i == 0) { g_count = 0u; g_sense = 0u; }
    for (int j = i; j < Tq*4; j += stride) {
        f_prod_pre0[j] = 0; f_prod_h0[j] = 0; f_prod_p1[j] = 0; f_prod_h1[j] = 0;
        f_cons_pre0[j] = 0; f_cons_p1[j] = 0;
    }
    for (int j = i; j < (Tq+1)*4; j += stride) {
        f_cons_h0[j] = 0; f_cons_h1[j] = 0;
    }
}

// ========================= persistent fused 2-layer scan =========================
// 128 blocks = 4 bands x (8 G0 + 8 G1 + 8 G2 + 8 G3). Self-timed per band via
// produced/consumed counters; NO global barrier after init.
//  G3: pre0[t] = x[:,t,:] @ Wih0^T + b        (ring slot t&3)
//  G0: h0[t]   = tanh(pre0[t] + h0[t-1] @ Whh0^T)
//  G1: p1[t]   = h0[t] @ Wih1^T + b
//  G2: h1[t]   = tanh(p1[t] + h1[t-1] @ Whh1^T)
__global__ void __launch_bounds__(256) k_scan(const float* __restrict__ x,
                                              const float* __restrict__ Wih0,
                                              const float* __restrict__ bih0,
                                              const float* __restrict__ bhh0,
                                              const float* __restrict__ Whh0,
                                              const float* __restrict__ Wih1,
                                              const float* __restrict__ bih1,
                                              const float* __restrict__ bhh1,
                                              const float* __restrict__ Whh1)
{
    extern __shared__ __align__(16) float smem[];
    float* sW = smem;               // persistent W tile
    float* sA = smem + Hq*WST;      // double-buffered dup-A chunks

    const int tid   = threadIdx.x;
    const int blk   = blockIdx.x;
    const int band  = blk & 3;          // batch-row band (4)
    const int c     = (blk >> 2) & 7;   // col tile within H (8)
    const int group = blk >> 5;         // 0..3
    const int m0    = band << 6;
    const int n0    = c << 6;
    const int tx = tid & 15, ty = tid >> 4;
    const int col = n0 + (tx << 2);

    // one-time: load this block's weight tile into smem
    if      (group == 0) preload_W(Whh0, Hq, n0, Hq, sW);
    else if (group == 1) preload_W(Wih1, Hq, n0, Hq, sW);
    else if (group == 2) preload_W(Whh1, Hq, n0, Hq, sW);
    else                 preload_W(Wih0, Dq, n0, Dq, sW);

    // zero the t=-1 slots (slot 3) of h0/h1 rings
    for (int i = blk*256 + tid; i < BHq; i += NBLK_SCAN*256) {
        g_h0r[3*(size_t)BHq + i] = 0.f;
        g_h1r[3*(size_t)BHq + i] = 0.f;
    }
    __threadfence();
    grid_barrier_once(NBLK_SCAN);

    float acc[4][4];

    if (group == 3) {
        // ---------------- pre0 producer ----------------
        float4 b1 = *(const float4*)(bih0 + col);
        float4 b2 = *(const float4*)(bhh0 + col);
        for (int t = 0; t < Tq; ++t) {
            gemm64_wp(x + (size_t)t*Dq, Tq*Dq, m0, sW, Dq, sA, acc);
            __syncthreads();
            if (tid == 0 && t >= 4)
                wait_flag(&f_cons_pre0[(t-4)*4 + band], 8);
            __syncthreads();
            float* dst = g_pre0r + (size_t)(t&3)*BHq;
            #pragma unroll
            for (int i = 0; i < 4; ++i) {
                int row = m0 + (ty << 2) + i;
                float4 o;
                o.x = acc[i][0] + b1.x + b2.x;
                o.y = acc[i][1] + b1.y + b2.y;
                o.z = acc[i][2] + b1.z + b2.z;
                o.w = acc[i][3] + b1.w + b2.w;
                *(float4*)(dst + (size_t)row*Hq + col) = o;
            }
            __syncthreads();
            if (tid == 0) { __threadfence(); atomicAdd(&f_prod_pre0[t*4 + band], 1); }
        }
    } else if (group == 0) {
        // ---------------- layer-0 recurrence ----------------
        for (int t = 0; t < Tq; ++t) {
            if (tid == 0) {
                if (t >= 1) wait_flag(&f_prod_h0[(t-1)*4 + band], 8);
                __threadfence();
            }
            __syncthreads();
            const float* A = g_h0r + (size_t)((t-1)&3)*BHq;
            gemm64_wp(A, Hq, m0, sW, Hq, sA, acc);
            __syncthreads();
            if (tid == 0) {
                atomicAdd(&f_cons_h0[t*4 + band], 1);        // consumed h0[t-1]
                wait_flag(&f_prod_pre0[t*4 + band], 8);
                if (t >= 3) {
                    int tm4 = t - 4;
                    wait_flag(&f_cons_h0[(tm4+1)*4 + band], (tm4 < 0) ? 8 : 16);
                }
                __threadfence();
            }
            __syncthreads();
            const float* pin = g_pre0r + (size_t)(t&3)*BHq;
            float* dst = g_h0r + (size_t)(t&3)*BHq;
            #pragma unroll
            for (int i = 0; i < 4; ++i) {
                int row = m0 + (ty << 2) + i;
                float4 p = __ldcg((const float4*)(pin + (size_t)row*Hq + col));
                float4 o;
                o.x = tanhf(acc[i][0] + p.x);
                o.y = tanhf(acc[i][1] + p.y);
                o.z = tanhf(acc[i][2] + p.z);
                o.w = tanhf(acc[i][3] + p.w);
                *(float4*)(dst + (size_t)row*Hq + col) = o;
            }
            __syncthreads();
            if (tid == 0) {
                __threadfence();
                atomicAdd(&f_prod_h0[t*4 + band], 1);
                atomicAdd(&f_cons_pre0[t*4 + band], 1);
            }
        }
    } else if (group == 1) {
        // ---------------- inter-layer GEMM ----------------
        float4 b1 = *(const float4*)(bih1 + col);
        float4 b2 = *(const float4*)(bhh1 + col);
        for (int t = 0; t < Tq; ++t) {
            if (tid == 0) {
                wait_flag(&f_prod_h0[t*4 + band], 8);
                __threadfence();
            }
            __syncthreads();
            const float* A = g_h0r + (size_t)(t&3)*BHq;
            gemm64_wp(A, Hq, m0, sW, Hq, sA, acc);
            __syncthreads();
            if (tid == 0) {
                atomicAdd(&f_cons_h0[(t+1)*4 + band], 1);    // consumed h0[t]
                if (t >= 4) wait_flag(&f_cons_p1[(t-4)*4 + band], 8);
            }
            __syncthreads();
            float* dst = g_p1r + (size_t)(t&3)*BHq;
            #pragma unroll
            for (int i = 0; i < 4; ++i) {
                int row = m0 + (ty << 2) + i;
                float4 o;
                o.x = acc[i][0] + b1.x + b2.x;
                o.y = acc[i][1] + b1.y + b2.y;
                o.z = acc[i][2] + b1.z + b2.z;
                o.w = acc[i][3] + b1.w + b2.w;
                *(float4*)(dst + (size_t)row*Hq + col) = o;
            }
            __syncthreads();
            if (tid == 0) { __threadfence(); atomicAdd(&f_prod_p1[t*4 + band], 1); }
        }
    } else {
        // ---------------- layer-1 recurrence ----------------
        for (int t = 0; t < Tq; ++t) {
            if (tid == 0) {
                if (t >= 1) wait_flag(&f_prod_h1[(t-1)*4 + band], 8);
                __threadfence();
            }
            __syncthreads();
            const float* A = g_h1r + (size_t)((t-1)&3)*BHq;
            gemm64_wp(A, Hq, m0, sW, Hq, sA, acc);
            __syncthreads();
            if (tid == 0) {
                atomicAdd(&f_cons_h1[t*4 + band], 1);        // consumed h1[t-1]
                wait_flag(&f_prod_p1[t*4 + band], 8);
                if (t >= 3) wait_flag(&f_cons_h1[(t-3)*4 + band], 8);
                __threadfence();
            }
            __syncthreads();
            const float* pin = g_p1r + (size_t)(t&3)*BHq;
            float* dst = g_h1r + (size_t)(t&3)*BHq;
            #pragma unroll
            for (int i = 0; i < 4; ++i) {
                int row = m0 + (ty << 2) + i;
                float4 p = __ldcg((const float4*)(pin + (size_t)row*Hq + col));
                float4 o;
                o.x = tanhf(acc[i][0] + p.x);
                o.y = tanhf(acc[i][1] + p.y);
                o.z = tanhf(acc[i][2] + p.z);
                o.w = tanhf(acc[i][3] + p.w);
                *(float4*)(dst + (size_t)row*Hq + col) = o;
            }
            __syncthreads();
            if (tid == 0) {
                __threadfence();
                atomicAdd(&f_prod_h1[t*4 + band], 1);
                atomicAdd(&f_cons_p1[t*4 + band], 1);
            }
        }
    }
}

// ---------------- head: z1 = relu(h1[511] @ Wf1^T + bf1) ----------------
__global__ void __launch_bounds__(256) k_fc1(const float* __restrict__ Wf1,
                                             const float* __restrict__ bf1)
{
    __shared__ __align__(16) float sA[2*SCH], sW[2*SCH];
    float acc[4][4];
    const int m0 = blockIdx.y << 6;
    const int n0 = blockIdx.x << 6;
    const float* A = g_h1r + (size_t)((Tq-1)&3)*BHq;   // slot 3
    gemm64s(A, Hq, m0, Wf1, Hq, n0, Hq, sA, sW, acc);

    const int tx = threadIdx.x & 15, ty = threadIdx.x >> 4;
    const int col = n0 + (tx << 2);
    float4 b = *(const float4*)(bf1 + col);
    #pragma unroll
    for (int i = 0; i < 4; ++i) {
        int row = m0 + (ty << 2) + i;
        float4 o;
        o.x = fmaxf(acc[i][0] + b.x, 0.f);
        o.y = fmaxf(acc[i][1] + b.y, 0.f);
        o.z = fmaxf(acc[i][2] + b.z, 0.f);
        o.w = fmaxf(acc[i][3] + b.w, 0.f);
        *(float4*)(g_z1 + (size_t)row*F1q + col) = o;
    }
}

// ---------------- head: out = z1 @ Wf2^T + bf2 ----------------
__global__ void __launch_bounds__(256) k_fc2(const float* __restrict__ Wf2,
                                             const float* __restrict__ bf2,
                                             float* __restrict__ out)
{
    __shared__ __align__(16) float sA[2*SCH], sW[2*SCH];
    float acc[4][4];
    const int m0 = blockIdx.y << 6;
    gemm64s(g_z1, F1q, m0, Wf2, F1q, 0, F1q, sA, sW, acc);

    const int tx = threadIdx.x & 15, ty = threadIdx.x >> 4;
    const int col = (tx << 2);
    float4 b = *(const float4*)(bf2 + col);
    #pragma unroll
    for (int i = 0; i < 4; ++i) {
        int row = m0 + (ty << 2) + i;
        float4 o;
        o.x = acc[i][0] + b.x;
        o.y = acc[i][1] + b.y;
        o.z = acc[i][2] + b.z;
        o.w = acc[i][3] + b.w;
        *(float4*)(out + (size_t)row*Oq + col) = o;
    }
}

// ---------------- launch ----------------
extern "C" void kernel_launch(void* const* d_in, const int* in_sizes, int n_in,
                              void* d_out, int out_size)
{
    (void)in_sizes; (void)n_in; (void)out_size;
    const float* x    = (const float*)d_in[0];
    const float* Wih0 = (const float*)d_in[1];
    const float* Whh0 = (const float*)d_in[2];
    const float* bih0 = (const float*)d_in[3];
    const float* bhh0 = (const float*)d_in[4];
    const float* Wih1 = (const float*)d_in[5];
    const float* Whh1 = (const float*)d_in[6];
    const float* bih1 = (const float*)d_in[7];
    const float* bhh1 = (const float*)d_in[8];
    const float* Wf1  = (const float*)d_in[9];
    const float* bf1  = (const float*)d_in[10];
    const float* Wf2  = (const float*)d_in[11];
    const float* bf2  = (const float*)d_in[12];
    float* out = (float*)d_out;

    cudaFuncSetAttribute(k_scan, cudaFuncAttributeMaxDynamicSharedMemorySize, SMEM_SCAN);

    k_reset<<<8, 256>>>();
    k_scan<<<NBLK_SCAN, 256, SMEM_SCAN>>>(x, Wih0, bih0, bhh0, Whh0,
                                          Wih1, bih1, bhh1, Whh1);
    k_fc1<<<dim3(F1q/64, Bq/64), 256>>>(Wf1, bf1);
    k_fc2<<<dim3(1, Bq/64), 256>>>(Wf2, bf2, out);
}

// round 8
// speedup vs baseline: 1.4039x; 1.4039x over previous
#include <cuda_runtime.h>
#include <math.h>

typedef unsigned long long ull;

#define Bq   256
#define Tq   512
#define Dq   256
#define Hq   512
#define F1q  128
#define Oq   64
#define BHq  (Bq*Hq)
#define NBLK_SCAN 128
#define RD   8                  // ring depth (slots)
#define RMASK (RD-1)
#define WST  68                 // persistent W smem stride (floats)
#define SCH  (16*68)            // one A smem chunk: 16 k-slices x 68-stride
#define SMEM_SCAN ((Hq*WST + 2*SCH) * 4)   // 147,968 B

// ---------------- scratch (device globals: allocation-free rule) ----------------
__device__ float g_pre0r[RD*(size_t)BHq];   // 8-slot rings, 4 MB each
__device__ float g_h0r [RD*(size_t)BHq];
__device__ float g_p1r [RD*(size_t)BHq];
__device__ float g_h1r [RD*(size_t)BHq];
__device__ float g_z1[Bq*F1q];
__device__ unsigned g_count;
__device__ volatile unsigned g_sense;

// per-(t,band) completion counters, each counts to 8 (one per col-tile block)
__device__ int f_pre0[Tq*4];   // pre0[t] stored
__device__ int f_g0 [Tq*4];    // h0[t] stored (G0 step t done; pre0[t] consumed)
__device__ int f_g1 [Tq*4];    // p1[t] stored (G1 step t done; h0[t] consumed)
__device__ int f_g2 [Tq*4];    // h1[t] stored (G2 step t done; p1[t] consumed)

// ---------------- packed f32x2 helpers ----------------
__device__ __forceinline__ ull pack2(float lo, float hi)
{
    ull v;
    asm("mov.b64 %0, {%1, %2};" : "=l"(v) : "f"(lo), "f"(hi));
    return v;
}
__device__ __forceinline__ void unpack2(ull v, float &lo, float &hi)
{
    asm("mov.b64 {%0, %1}, %2;" : "=f"(lo), "=f"(hi) : "l"(v));
}
__device__ __forceinline__ void ffma2(ull &d, ull a, ull b)
{
    asm("fma.rn.f32x2 %0, %1, %2, %0;" : "+l"(d) : "l"(a), "l"(b));
}

// ---------------- acquire-load poll (tight, no nanosleep) ----------------
__device__ __forceinline__ int ld_acq(const int* p)
{
    int v;
    asm volatile("ld.acquire.gpu.global.s32 %0, [%1];" : "=r"(v) : "l"(p) : "memory");
    return v;
}
__device__ __forceinline__ void wait8(const int* p)
{
    while (ld_acq(p) < 8) { }
}

// ---------------- one-time grid barrier for init ----------------
__device__ __forceinline__ void grid_barrier_once(unsigned nblk)
{
    __syncthreads();
    if (threadIdx.x == 0) {
        if (atomicAdd(&g_count, 1u) == nblk - 1u) {
            __threadfence();
            g_sense = 1u;
        } else {
            while (g_sense != 1u) { __nanosleep(32); }
        }
    }
    __syncthreads();
}

// ======== scan GEMM core, persistent-W-in-smem:  C64x64 = A(:,K) * Wsmem^T ========
// 256 threads, thread (tx,ty) owns 4x4 at (ty*4, tx*4). A prefetched 2 chunks deep.
__device__ __forceinline__ void gemm64_wp(const float* __restrict__ A, int lda, int m0,
                                          const float* __restrict__ sW, int K,
                                          float* sA, float accf[4][4])
{
    const int tid  = threadIdx.x;
    const int tx   = tid & 15, ty = tid >> 4;
    const int lrow = tid >> 2;          // 0..63
    const int lcg  = (tid & 3) << 2;    // 0,4,8,12
    const float* ap = A + (size_t)(m0 + lrow) * lda + lcg;

    ull acc[2][4];
    #pragma unroll
    for (int i = 0; i < 2; ++i)
        #pragma unroll
        for (int j = 0; j < 4; ++j) acc[i][j] = 0ull;

    float4 av0 = __ldcg((const float4*)ap);
    float4 av1 = __ldcg((const float4*)(ap + 16));

    int buf = 0;
    for (int kc = 0; kc < K; kc += 16, buf ^= 1) {
        float* sAb = sA + buf * SCH;
        sAb[(lcg+0)*68 + lrow] = av0.x;
        sAb[(lcg+1)*68 + lrow] = av0.y;
        sAb[(lcg+2)*68 + lrow] = av0.z;
        sAb[(lcg+3)*68 + lrow] = av0.w;
        __syncthreads();
        av0 = av1;
        if (kc + 32 < K)
            av1 = __ldcg((const float4*)(ap + kc + 32));
        const float* sWk = sW + kc * WST;
        #pragma unroll
        for (int k = 0; k < 16; ++k) {
            const float* ar = sAb + k*68 + (ty << 2);
            ull a01 = *(const ull*)ar;        // rows +0,+1
            ull a23 = *(const ull*)(ar + 2);  // rows +2,+3
            float4 w = *(const float4*)(sWk + k*WST + (tx << 2));
            ull b0 = pack2(w.x, w.x);
            ull b1 = pack2(w.y, w.y);
            ull b2 = pack2(w.z, w.z);
            ull b3 = pack2(w.w, w.w);
            ffma2(acc[0][0], a01, b0); ffma2(acc[0][1], a01, b1);
            ffma2(acc[0][2], a01, b2); ffma2(acc[0][3], a01, b3);
            ffma2(acc[1][0], a23, b0); ffma2(acc[1][1], a23, b1);
            ffma2(acc[1][2], a23, b2); ffma2(acc[1][3], a23, b3);
        }
        // next store targets the other buffer; ordered by the next sync.
    }

    #pragma unroll
    for (int i = 0; i < 2; ++i)
        #pragma unroll
        for (int j = 0; j < 4; ++j)
            unpack2(acc[i][j], accf[2*i][j], accf[2*i + 1][j]);
}

// preload one 64-row W tile (rows n0.., K cols) into sW[k*WST + n]
__device__ __forceinline__ void preload_W(const float* __restrict__ W, int ldw, int n0,
                                          int K, float* sW)
{
    const int KQ = K >> 2;
    for (int i = threadIdx.x; i < (KQ << 6); i += 256) {
        int n  = i / KQ;
        int k4 = i - n * KQ;
        float4 v = *(const float4*)(W + (size_t)(n0 + n) * ldw + (k4 << 2));
        sW[(4*k4+0)*WST + n] = v.x;
        sW[(4*k4+1)*WST + n] = v.y;
        sW[(4*k4+2)*WST + n] = v.z;
        sW[(4*k4+3)*WST + n] = v.w;
    }
}

// ---------------- legacy chunked GEMM core (tiny head kernels) ----------------
__device__ __forceinline__ void gemm64s(const float* __restrict__ A, int lda, int m0,
                                        const float* __restrict__ W, int ldw, int n0,
                                        int K, float* sA, float* sW, float accf[4][4])
{
    const int tid  = threadIdx.x;
    const int tx   = tid & 15, ty = tid >> 4;
    const int lrow = tid >> 2;
    const int lcg  = (tid & 3) << 2;
    const float* ap = A + (size_t)(m0 + lrow) * lda + lcg;
    const float* wp = W + (size_t)(n0 + lrow) * ldw + lcg;

    ull acc[2][4];
    #pragma unroll
    for (int i = 0; i < 2; ++i)
        #pragma unroll
        for (int j = 0; j < 4; ++j) acc[i][j] = 0ull;

    float4 av = __ldcg((const float4*)ap);
    float4 wv = *(const float4*)wp;

    int buf = 0;
    for (int kc = 0; kc < K; kc += 16, buf ^= 1) {
        float* sAb = sA + buf * SCH;
        float* sWb = sW + buf * SCH;
        sAb[(lcg+0)*68 + lrow] = av.x;
        sAb[(lcg+1)*68 + lrow] = av.y;
        sAb[(lcg+2)*68 + lrow] = av.z;
        sAb[(lcg+3)*68 + lrow] = av.w;
        sWb[(lcg+0)*68 + lrow] = wv.x;
        sWb[(lcg+1)*68 + lrow] = wv.y;
        sWb[(lcg+2)*68 + lrow] = wv.z;
        sWb[(lcg+3)*68 + lrow] = wv.w;
        __syncthreads();
        if (kc + 16 < K) {
            av = __ldcg((const float4*)(ap + kc + 16));
            wv = *(const float4*)(wp + kc + 16);
        }
        #pragma unroll
        for (int k = 0; k < 16; ++k) {
            const float* ar = sAb + k*68 + (ty << 2);
            ull a01 = *(const ull*)ar;
            ull a23 = *(const ull*)(ar + 2);
            float4 w = *(const float4*)(sWb + k*68 + (tx << 2));
            ull b0 = pack2(w.x, w.x);
            ull b1 = pack2(w.y, w.y);
            ull b2 = pack2(w.z, w.z);
            ull b3 = pack2(w.w, w.w);
            ffma2(acc[0][0], a01, b0); ffma2(acc[0][1], a01, b1);
            ffma2(acc[0][2], a01, b2); ffma2(acc[0][3], a01, b3);
            ffma2(acc[1][0], a23, b0); ffma2(acc[1][1], a23, b1);
            ffma2(acc[1][2], a23, b2); ffma2(acc[1][3], a23, b3);
        }
    }

    #pragma unroll
    for (int i = 0; i < 2; ++i)
        #pragma unroll
        for (int j = 0; j < 4; ++j)
            unpack2(acc[i][j], accf[2*i][j], accf[2*i + 1][j]);
}

// ---------------- reset counters/flags ----------------
__global__ void k_reset()
{
    int i = blockIdx.x*blockDim.x + threadIdx.x;
    int stride = gridDim.x*blockDim.x;
    if (i == 0) { g_count = 0u; g_sense = 0u; }
    for (int j = i; j < Tq*4; j += stride) {
        f_pre0[j] = 0; f_g0[j] = 0; f_g1[j] = 0; f_g2[j] = 0;
    }
}

// ========================= persistent fused 2-layer scan =========================
// 128 blocks = 4 groups x 4 bands x 8 col-tiles. Self-timed per band; no global
// barrier after init. Rings are 8 deep; publish = fence + atomicAdd (tid 0),
// wait = tight ld.acquire poll (tid 0). Ring reads use __ldcg (L2-coherent).
//  G3: pre0[t] = x[:,t,:] @ Wih0^T + b
//  G0: h0[t]   = tanh(pre0[t] + h0[t-1] @ Whh0^T)      <- critical chain
//  G1: p1[t]   = h0[t] @ Wih1^T + b
//  G2: h1[t]   = tanh(p1[t] + h1[t-1] @ Whh1^T)        <- critical chain
__global__ void __launch_bounds__(256) k_scan(const float* __restrict__ x,
                                              const float* __restrict__ Wih0,
                                              const float* __restrict__ bih0,
                                              const float* __restrict__ bhh0,
                                              const float* __restrict__ Whh0,
                                              const float* __restrict__ Wih1,
                                              const float* __restrict__ bih1,
                                              const float* __restrict__ bhh1,
                                              const float* __restrict__ Whh1)
{
    extern __shared__ __align__(16) float smem[];
    float* sW = smem;               // persistent W tile
    float* sA = smem + Hq*WST;      // double-buffered A chunks

    const int tid   = threadIdx.x;
    const int blk   = blockIdx.x;
    const int band  = blk & 3;          // batch-row band (4)
    const int c     = (blk >> 2) & 7;   // col tile within H (8)
    const int group = blk >> 5;         // 0..3
    const int m0    = band << 6;
    const int n0    = c << 6;
    const int tx = tid & 15, ty = tid >> 4;
    const int col = n0 + (tx << 2);

    // one-time: load this block's weight tile into smem
    if      (group == 0) preload_W(Whh0, Hq, n0, Hq, sW);
    else if (group == 1) preload_W(Wih1, Hq, n0, Hq, sW);
    else if (group == 2) preload_W(Whh1, Hq, n0, Hq, sW);
    else                 preload_W(Wih0, Dq, n0, Dq, sW);

    // zero the t=-1 slots (slot RD-1) of h0/h1 rings
    for (int i = blk*256 + tid; i < BHq; i += NBLK_SCAN*256) {
        g_h0r[(size_t)(RD-1)*BHq + i] = 0.f;
        g_h1r[(size_t)(RD-1)*BHq + i] = 0.f;
    }
    __threadfence();
    grid_barrier_once(NBLK_SCAN);

    float acc[4][4];

    if (group == 3) {
        // ---------------- pre0 producer (runs ahead; gated by G0 at t-RD) ----------------
        float4 b1 = *(const float4*)(bih0 + col);
        float4 b2 = *(const float4*)(bhh0 + col);
        for (int t = 0; t < Tq; ++t) {
            gemm64_wp(x + (size_t)t*Dq, Tq*Dq, m0, sW, Dq, sA, acc);
            __syncthreads();
            if (tid == 0 && t >= RD)
                wait8(&f_g0[(t-RD)*4 + band]);   // pre0 slot (t&RMASK) consumed
            __syncthreads();
            float* dst = g_pre0r + (size_t)(t & RMASK)*BHq;
            #pragma unroll
            for (int i = 0; i < 4; ++i) {
                int row = m0 + (ty << 2) + i;
                float4 o;
                o.x = acc[i][0] + b1.x + b2.x;
                o.y = acc[i][1] + b1.y + b2.y;
                o.z = acc[i][2] + b1.z + b2.z;
                o.w = acc[i][3] + b1.w + b2.w;
                *(float4*)(dst + (size_t)row*Hq + col) = o;
            }
            __syncthreads();
            if (tid == 0) { __threadfence(); atomicAdd(&f_pre0[t*4 + band], 1); }
        }
    } else if (group == 0) {
        // ---------------- layer-0 recurrence (critical chain) ----------------
        for (int t = 0; t < Tq; ++t) {
            if (tid == 0) {
                if (t >= 1)  wait8(&f_g0[(t-1)*4 + band]);   // h0[t-1] ready
                wait8(&f_pre0[t*4 + band]);                  // pre0[t] ready
                if (t >= RD) wait8(&f_g1[(t-RD)*4 + band]);  // h0 slot reusable
            }
            __syncthreads();
            const float* A = g_h0r + (size_t)((t-1) & RMASK)*BHq;
            gemm64_wp(A, Hq, m0, sW, Hq, sA, acc);
            __syncthreads();
            const float* pin = g_pre0r + (size_t)(t & RMASK)*BHq;
            float* dst = g_h0r + (size_t)(t & RMASK)*BHq;
            #pragma unroll
            for (int i = 0; i < 4; ++i) {
                int row = m0 + (ty << 2) + i;
                float4 p = __ldcg((const float4*)(pin + (size_t)row*Hq + col));
                float4 o;
                o.x = tanhf(acc[i][0] + p.x);
                o.y = tanhf(acc[i][1] + p.y);
                o.z = tanhf(acc[i][2] + p.z);
                o.w = tanhf(acc[i][3] + p.w);
                *(float4*)(dst + (size_t)row*Hq + col) = o;
            }
            __syncthreads();
            if (tid == 0) { __threadfence(); atomicAdd(&f_g0[t*4 + band], 1); }
        }
    } else if (group == 1) {
        // ---------------- inter-layer GEMM ----------------
        float4 b1 = *(const float4*)(bih1 + col);
        float4 b2 = *(const float4*)(bhh1 + col);
        for (int t = 0; t < Tq; ++t) {
            if (tid == 0) {
                wait8(&f_g0[t*4 + band]);                    // h0[t] ready
                if (t >= RD) wait8(&f_g2[(t-RD)*4 + band]);  // p1 slot reusable
            }
            __syncthreads();
            const float* A = g_h0r + (size_t)(t & RMASK)*BHq;
            gemm64_wp(A, Hq, m0, sW, Hq, sA, acc);
            __syncthreads();
            float* dst = g_p1r + (size_t)(t & RMASK)*BHq;
            #pragma unroll
            for (int i = 0; i < 4; ++i) {
                int row = m0 + (ty << 2) + i;
                float4 o;
                o.x = acc[i][0] + b1.x + b2.x;
                o.y = acc[i][1] + b1.y + b2.y;
                o.z = acc[i][2] + b1.z + b2.z;
                o.w = acc[i][3] + b1.w + b2.w;
                *(float4*)(dst + (size_t)row*Hq + col) = o;
            }
            __syncthreads();
            if (tid == 0) { __threadfence(); atomicAdd(&f_g1[t*4 + band], 1); }
        }
    } else {
        // ---------------- layer-1 recurrence (critical chain) ----------------
        for (int t = 0; t < Tq; ++t) {
            if (tid == 0) {
                if (t >= 1) wait8(&f_g2[(t-1)*4 + band]);    // h1[t-1] ready
                wait8(&f_g1[t*4 + band]);                    // p1[t] ready
            }
            __syncthreads();
            const float* A = g_h1r + (size_t)((t-1) & RMASK)*BHq;
            gemm64_wp(A, Hq, m0, sW, Hq, sA, acc);
            __syncthreads();
            const float* pin = g_p1r + (size_t)(t & RMASK)*BHq;
            float* dst = g_h1r + (size_t)(t & RMASK)*BHq;
            #pragma unroll
            for (int i = 0; i < 4; ++i) {
                int row = m0 + (ty << 2) + i;
                float4 p = __ldcg((const float4*)(pin + (size_t)row*Hq + col));
                float4 o;
                o.x = tanhf(acc[i][0] + p.x);
                o.y = tanhf(acc[i][1] + p.y);
                o.z = tanhf(acc[i][2] + p.z);
                o.w = tanhf(acc[i][3] + p.w);
                *(float4*)(dst + (size_t)row*Hq + col) = o;
            }
            __syncthreads();
            if (tid == 0) { __threadfence(); atomicAdd(&f_g2[t*4 + band], 1); }
        }
    }
}

// ---------------- head: z1 = relu(h1[511] @ Wf1^T + bf1) ----------------
__global__ void __launch_bounds__(256) k_fc1(const float* __restrict__ Wf1,
                                             const float* __restrict__ bf1)
{
    __shared__ __align__(16) float sA[2*SCH], sW[2*SCH];
    float acc[4][4];
    const int m0 = blockIdx.y << 6;
    const int n0 = blockIdx.x << 6;
    const float* A = g_h1r + (size_t)((Tq-1) & RMASK)*BHq;   // slot 7
    gemm64s(A, Hq, m0, Wf1, Hq, n0, Hq, sA, sW, acc);

    const int tx = threadIdx.x & 15, ty = threadIdx.x >> 4;
    const int col = n0 + (tx << 2);
    float4 b = *(const float4*)(bf1 + col);
    #pragma unroll
    for (int i = 0; i < 4; ++i) {
        int row = m0 + (ty << 2) + i;
        float4 o;
        o.x = fmaxf(acc[i][0] + b.x, 0.f);
        o.y = fmaxf(acc[i][1] + b.y, 0.f);
        o.z = fmaxf(acc[i][2] + b.z, 0.f);
        o.w = fmaxf(acc[i][3] + b.w, 0.f);
        *(float4*)(g_z1 + (size_t)row*F1q + col) = o;
    }
}

// ---------------- head: out = z1 @ Wf2^T + bf2 ----------------
__global__ void __launch_bounds__(256) k_fc2(const float* __restrict__ Wf2,
                                             const float* __restrict__ bf2,
                                             float* __restrict__ out)
{
    __shared__ __align__(16) float sA[2*SCH], sW[2*SCH];
    float acc[4][4];
    const int m0 = blockIdx.y << 6;
    gemm64s(g_z1, F1q, m0, Wf2, F1q, 0, F1q, sA, sW, acc);

    const int tx = threadIdx.x & 15, ty = threadIdx.x >> 4;
    const int col = (tx << 2);
    float4 b = *(const float4*)(bf2 + col);
    #pragma unroll
    for (int i = 0; i < 4; ++i) {
        int row = m0 + (ty << 2) + i;
        float4 o;
        o.x = acc[i][0] + b.x;
        o.y = acc[i][1] + b.y;
        o.z = acc[i][2] + b.z;
        o.w = acc[i][3] + b.w;
        *(float4*)(out + (size_t)row*Oq + col) = o;
    }
}

// ---------------- launch ----------------
extern "C" void kernel_launch(void* const* d_in, const int* in_sizes, int n_in,
                              void* d_out, int out_size)
{
    (void)in_sizes; (void)n_in; (void)out_size;
    const float* x    = (const float*)d_in[0];
    const float* Wih0 = (const float*)d_in[1];
    const float* Whh0 = (const float*)d_in[2];
    const float* bih0 = (const float*)d_in[3];
    const float* bhh0 = (const float*)d_in[4];
    const float* Wih1 = (const float*)d_in[5];
    const float* Whh1 = (const float*)d_in[6];
    const float* bih1 = (const float*)d_in[7];
    const float* bhh1 = (const float*)d_in[8];
    const float* Wf1  = (const float*)d_in[9];
    const float* bf1  = (const float*)d_in[10];
    const float* Wf2  = (const float*)d_in[11];
    const float* bf2  = (const float*)d_in[12];
    float* out = (float*)d_out;

    cudaFuncSetAttribute(k_scan, cudaFuncAttributeMaxDynamicSharedMemorySize, SMEM_SCAN);

    k_reset<<<8, 256>>>();
    k_scan<<<NBLK_SCAN, 256, SMEM_SCAN>>>(x, Wih0, bih0, bhh0, Whh0,
                                          Wih1, bih1, bhh1, Whh1);
    k_fc1<<<dim3(F1q/64, Bq/64), 256>>>(Wf1, bf1);
    k_fc2<<<dim3(1, Bq/64), 256>>>(Wf2, bf2, out);
}